// round 1
// baseline (speedup 1.0000x reference)
#include <cuda_runtime.h>
#include <math.h>

#define BB 64
#define TT 2048
#define HH 256
#define CH 128
#define NCHUNK 16              // TT / CH
#define NBLK (BB * NCHUNK)     // 1024
#define FAN_EPS 1e-4f

// Deterministic two-stage reduction scratch (no atomics).
__device__ float g_psum[2][NBLK][HH];
__device__ float g_psumsq[2][NBLK][HH];
__device__ float g_cA[2][HH];   // gamma/sd per slice
__device__ float g_cB[2][HH];   // beta - mu*gamma/sd per slice

// Window stats: mu and clamped inverse-sd.
// inv_sd = min(rsqrt(var), 1/EPS) is exactly max(sqrt(var), EPS) inverted.
__device__ __forceinline__ void win_stats(float s1, float s2, float invw,
                                          float invwm1, float& mu, float& isd) {
    mu = s1 * invw;
    float var = (s2 - s1 * s1 * invw) * invwm1;
    var = fmaxf(var, 0.0f);
    isd = fminf(rsqrtf(var), 1.0f / FAN_EPS);   // var==0 -> inf -> clamp
}

template <bool WRITE>
__global__ __launch_bounds__(HH)
void fan_kernel(const float* __restrict__ x, const float* __restrict__ alpha,
                float* __restrict__ out) {
    const int c  = blockIdx.x & (NCHUNK - 1);
    const int b  = blockIdx.x >> 4;
    const int h  = threadIdx.x;
    const int t0 = c * CH;
    const float* px = x + ((size_t)b * TT) * HH + h;

    // softmax over the 3 window weights for this channel
    float a0 = alpha[h * 3 + 0], a1 = alpha[h * 3 + 1], a2 = alpha[h * 3 + 2];
    float mx = fmaxf(a0, fmaxf(a1, a2));
    float e0 = expf(a0 - mx), e1 = expf(a1 - mx), e2 = expf(a2 - mx);
    float inv = 1.0f / (e0 + e1 + e2);
    const float al5 = e0 * inv, al10 = e1 * inv, al20 = e2 * inv;

    float s1_5 = 0, s2_5 = 0, s1_10 = 0, s2_10 = 0, s1_20 = 0, s2_20 = 0;
    // first-full-window stats (edge padding), used only for chunk 0, t < w-1
    float fmu5 = 0, fis5 = 0, fmu10 = 0, fis10 = 0, fmu20 = 0, fis20 = 0;

    if (c == 0) {
        float s1 = 0, s2 = 0;
#pragma unroll
        for (int j = 0; j < 20; j++) {
            float v = px[j * HH];
            s1 += v; s2 += v * v;
            if (j == 4)  win_stats(s1, s2, 0.2f,  0.25f,        fmu5,  fis5);
            if (j == 9)  win_stats(s1, s2, 0.1f,  1.0f / 9.0f,  fmu10, fis10);
            if (j == 19) win_stats(s1, s2, 0.05f, 1.0f / 19.0f, fmu20, fis20);
        }
    } else {
        // halo: x[t0-20 .. t0-1]
#pragma unroll
        for (int j = 0; j < 20; j++) {
            float v = px[(t0 - 20 + j) * HH];
            s1_20 += v; s2_20 += v * v;
            if (j >= 10) { s1_10 += v; s2_10 += v * v; }
            if (j >= 15) { s1_5  += v; s2_5  += v * v; }
        }
    }

    // SAN affine coefficients — uniform per chunk (boundaries 1024/1536 are
    // multiples of CH): region0 = slice0 only, region1 = overlap, region2 = slice1.
    float cA = 0.0f, cB = 0.0f;
    if (WRITE) {
        float A0 = g_cA[0][h], B0 = g_cB[0][h];
        float A1 = g_cA[1][h], B1 = g_cB[1][h];
        const float inv1 = 1.0f / (1.0f + FAN_EPS);
        const float inv2 = 1.0f / (2.0f + FAN_EPS);
        if (c < 8)       { cA = A0 * inv1;        cB = B0 * inv1; }
        else if (c < 12) { cA = (A0 + A1) * inv2; cB = (B0 + B1) * inv2; }
        else             { cA = A1 * inv1;        cB = B1 * inv1; }
    }

    float accS = 0.0f, accQ = 0.0f;
    float* pout = out + ((size_t)b * TT) * HH + h;

#pragma unroll 4
    for (int t = t0; t < t0 + CH; ++t) {
        float xt  = px[t * HH];
        float x5  = (t >= 5)  ? px[(t - 5)  * HH] : 0.0f;
        float x10 = (t >= 10) ? px[(t - 10) * HH] : 0.0f;
        float x20 = (t >= 20) ? px[(t - 20) * HH] : 0.0f;
        float xt2 = xt * xt;
        s1_5  += xt - x5;   s2_5  += xt2 - x5  * x5;
        s1_10 += xt - x10;  s2_10 += xt2 - x10 * x10;
        s1_20 += xt - x20;  s2_20 += xt2 - x20 * x20;

        float mu5, is5, mu10, is10, mu20, is20;
        win_stats(s1_5,  s2_5,  0.2f,  0.25f,        mu5,  is5);
        win_stats(s1_10, s2_10, 0.1f,  1.0f / 9.0f,  mu10, is10);
        win_stats(s1_20, s2_20, 0.05f, 1.0f / 19.0f, mu20, is20);
        // edge padding (only ever true for chunk 0)
        if (t < 4)  { mu5  = fmu5;  is5  = fis5;  }
        if (t < 9)  { mu10 = fmu10; is10 = fis10; }
        if (t < 19) { mu20 = fmu20; is20 = fis20; }

        float f = (xt - mu5)  * is5  * al5
                + (xt - mu10) * is10 * al10
                + (xt - mu20) * is20 * al20;

        if (WRITE) {
            pout[t * HH] = xt + f * cA + cB;
        } else {
            accS += f;
            accQ += f * f;
        }
    }

    if (!WRITE) {
        const int blk = blockIdx.x;
        const bool in0 = (c < 12);   // t < 1536
        const bool in1 = (c >= 8);   // t >= 1024
        g_psum[0][blk][h]   = in0 ? accS : 0.0f;
        g_psumsq[0][blk][h] = in0 ? accQ : 0.0f;
        g_psum[1][blk][h]   = in1 ? accS : 0.0f;
        g_psumsq[1][blk][h] = in1 ? accQ : 0.0f;
    }
}

__global__ __launch_bounds__(HH)
void stats_kernel(const float* __restrict__ gamma, const float* __restrict__ beta) {
    const int s = blockIdx.x;   // slice 0 or 1
    const int h = threadIdx.x;
    double S = 0.0, Q = 0.0;
    for (int blk = 0; blk < NBLK; ++blk) {
        S += (double)g_psum[s][blk][h];
        Q += (double)g_psumsq[s][blk][h];
    }
    const double n  = (s == 0) ? (double)BB * 1536.0 : (double)BB * 1024.0;
    double mu  = S / n;
    double var = (Q - S * S / n) / (n - 1.0);
    if (var < 0.0) var = 0.0;
    double sd = sqrt(var);
    if (sd < 1e-4) sd = 1e-4;
    float g  = gamma[s * HH + h];
    float be = beta[s * HH + h];
    float a  = (float)((double)g / sd);
    g_cA[s][h] = a;
    g_cB[s][h] = be - (float)mu * a;
}

extern "C" void kernel_launch(void* const* d_in, const int* in_sizes, int n_in,
                              void* d_out, int out_size) {
    (void)in_sizes; (void)n_in; (void)out_size;
    const float* x     = (const float*)d_in[0];
    const float* alpha = (const float*)d_in[1];
    const float* gamma = (const float*)d_in[2];
    const float* beta  = (const float*)d_in[3];
    float* out = (float*)d_out;

    fan_kernel<false><<<NBLK, HH>>>(x, alpha, nullptr);
    stats_kernel<<<2, HH>>>(gamma, beta);
    fan_kernel<true><<<NBLK, HH>>>(x, alpha, out);
}

// round 2
// speedup vs baseline: 3.7037x; 3.7037x over previous
#include <cuda_runtime.h>
#include <math.h>

#define BB 64
#define TT 2048
#define HH 256
#define CH 128
#define NCHUNK 16              // TT / CH
#define NBLK (BB * NCHUNK)     // 1024
#define FAN_EPS 1e-4f

// Transposed partial layout: [slice][h][blk] -> coalesced reduction reads.
__device__ float g_psum[2][HH][NBLK];
__device__ float g_psumsq[2][HH][NBLK];
__device__ float g_cA[2][HH];   // gamma/sd per slice
__device__ float g_cB[2][HH];   // beta - mu*gamma/sd per slice

// mu and clamped inverse-sd: inv_sd = min(rsqrt(var), 1/EPS) is exactly
// 1 / max(sqrt(var), EPS).
__device__ __forceinline__ void win_stats(float s1, float s2, float invw,
                                          float invwm1, float& mu, float& isd) {
    mu = s1 * invw;
    float var = fmaf(-s1, mu, s2) * invwm1;
    var = fmaxf(var, 0.0f);
    isd = fminf(rsqrtf(var), 1.0f / FAN_EPS);
}

template <bool WRITE, bool EDGE>
__device__ __forceinline__ void process_chunk(
    const float* __restrict__ px, float* __restrict__ pout, int t0,
    float al5, float al10, float al20, float cA, float cB,
    float& accS, float& accQ)
{
    float hist[32];
    float s1_5 = 0, s2_5 = 0, s1_10 = 0, s2_10 = 0, s1_20 = 0, s2_20 = 0;
    float fmu5 = 0, fis5 = 0, fmu10 = 0, fis10 = 0, fmu20 = 0, fis20 = 0;

    if (EDGE) {
        // chunk 0: nothing before t=0; ring starts zeroed, first-window stats
        // (edge padding) computed from x[0..19].
#pragma unroll
        for (int j = 0; j < 32; j++) hist[j] = 0.0f;
        float s1 = 0, s2 = 0;
#pragma unroll
        for (int j = 0; j < 20; j++) {
            float v = px[j * HH];
            s1 += v; s2 = fmaf(v, v, s2);
            if (j == 4)  win_stats(s1, s2, 0.2f,  0.25f,        fmu5,  fis5);
            if (j == 9)  win_stats(s1, s2, 0.1f,  1.0f / 9.0f,  fmu10, fis10);
            if (j == 19) win_stats(s1, s2, 0.05f, 1.0f / 19.0f, fmu20, fis20);
        }
    } else {
        // preload halo x[t0-32 .. t0-1]; t0 % 32 == 0 keeps ring phase aligned.
#pragma unroll
        for (int j = 0; j < 32; j++) hist[j] = px[(t0 - 32 + j) * HH];
#pragma unroll
        for (int j = 12; j < 32; j++) {
            float v = hist[j];
            s1_20 += v; s2_20 = fmaf(v, v, s2_20);
            if (j >= 22) { s1_10 += v; s2_10 = fmaf(v, v, s2_10); }
            if (j >= 27) { s1_5  += v; s2_5  = fmaf(v, v, s2_5);  }
        }
    }

    const float* p = px + (size_t)t0 * HH;
    float* po = pout + (size_t)t0 * HH;

#pragma unroll 1
    for (int base = 0; base < CH; base += 32) {
#pragma unroll
        for (int u = 0; u < 32; ++u) {
            float xt  = p[u * HH];
            float x5  = hist[(u + 27) & 31];
            float x10 = hist[(u + 22) & 31];
            float x20 = hist[(u + 12) & 31];
            hist[u] = xt;
            float xt2 = xt * xt;
            s1_5  = (s1_5  + xt) - x5;   s2_5  = fmaf(-x5,  x5,  s2_5  + xt2);
            s1_10 = (s1_10 + xt) - x10;  s2_10 = fmaf(-x10, x10, s2_10 + xt2);
            s1_20 = (s1_20 + xt) - x20;  s2_20 = fmaf(-x20, x20, s2_20 + xt2);

            float mu5, is5, mu10, is10, mu20, is20;
            win_stats(s1_5,  s2_5,  0.2f,  0.25f,        mu5,  is5);
            win_stats(s1_10, s2_10, 0.1f,  1.0f / 9.0f,  mu10, is10);
            win_stats(s1_20, s2_20, 0.05f, 1.0f / 19.0f, mu20, is20);

            if (EDGE) {
                int t = base + u;          // t0 == 0 here
                if (t < 4)  { mu5  = fmu5;  is5  = fis5;  }
                if (t < 9)  { mu10 = fmu10; is10 = fis10; }
                if (t < 19) { mu20 = fmu20; is20 = fis20; }
            }

            float w5 = is5 * al5, w10 = is10 * al10, w20 = is20 * al20;
            float m  = fmaf(mu20, w20, fmaf(mu10, w10, mu5 * w5));
            float f  = fmaf(xt, (w5 + w10) + w20, -m);

            if (WRITE) {
                po[u * HH] = fmaf(f, cA, xt) + cB;
            } else {
                accS += f;
                accQ = fmaf(f, f, accQ);
            }
        }
        p  += 32 * HH;
        po += 32 * HH;
    }
}

template <bool WRITE>
__global__ __launch_bounds__(HH, 4)
void fan_kernel(const float* __restrict__ x, const float* __restrict__ alpha,
                float* __restrict__ out) {
    const int c  = blockIdx.x & (NCHUNK - 1);
    const int b  = blockIdx.x >> 4;
    const int h  = threadIdx.x;
    const int t0 = c * CH;
    const float* px = x + ((size_t)b * TT) * HH + h;
    float* pout = out + ((size_t)b * TT) * HH + h;

    // softmax over the 3 window weights for this channel
    float a0 = alpha[h * 3 + 0], a1 = alpha[h * 3 + 1], a2 = alpha[h * 3 + 2];
    float mx = fmaxf(a0, fmaxf(a1, a2));
    float e0 = expf(a0 - mx), e1 = expf(a1 - mx), e2 = expf(a2 - mx);
    float inv = 1.0f / (e0 + e1 + e2);
    const float al5 = e0 * inv, al10 = e1 * inv, al20 = e2 * inv;

    // SAN affine coefficients — uniform per chunk (slice boundaries 1024/1536
    // are multiples of CH).
    float cA = 0.0f, cB = 0.0f;
    if (WRITE) {
        float A0 = g_cA[0][h], B0 = g_cB[0][h];
        float A1 = g_cA[1][h], B1 = g_cB[1][h];
        const float inv1 = 1.0f / (1.0f + FAN_EPS);
        const float inv2 = 1.0f / (2.0f + FAN_EPS);
        if (c < 8)       { cA = A0 * inv1;        cB = B0 * inv1; }
        else if (c < 12) { cA = (A0 + A1) * inv2; cB = (B0 + B1) * inv2; }
        else             { cA = A1 * inv1;        cB = B1 * inv1; }
    }

    float accS = 0.0f, accQ = 0.0f;
    if (c == 0)
        process_chunk<WRITE, true >(px, pout, t0, al5, al10, al20, cA, cB, accS, accQ);
    else
        process_chunk<WRITE, false>(px, pout, t0, al5, al10, al20, cA, cB, accS, accQ);

    if (!WRITE) {
        const int blk = blockIdx.x;
        const bool in0 = (c < 12);   // t < 1536
        const bool in1 = (c >= 8);   // t >= 1024
        g_psum[0][h][blk]   = in0 ? accS : 0.0f;
        g_psumsq[0][h][blk] = in0 ? accQ : 0.0f;
        g_psum[1][h][blk]   = in1 ? accS : 0.0f;
        g_psumsq[1][h][blk] = in1 ? accQ : 0.0f;
    }
}

// One block per (slice, h): 256 threads tree-reduce the 1024 partials.
__global__ __launch_bounds__(256)
void stats_kernel(const float* __restrict__ gamma, const float* __restrict__ beta) {
    const int s = blockIdx.x >> 8;
    const int h = blockIdx.x & (HH - 1);
    const int tid = threadIdx.x;

    double dS = 0.0, dQ = 0.0;
#pragma unroll
    for (int i = 0; i < NBLK / 256; ++i) {
        dS += (double)g_psum[s][h][tid + i * 256];
        dQ += (double)g_psumsq[s][h][tid + i * 256];
    }
    __shared__ double shS[256], shQ[256];
    shS[tid] = dS; shQ[tid] = dQ;
    __syncthreads();
    for (int off = 128; off > 0; off >>= 1) {
        if (tid < off) { shS[tid] += shS[tid + off]; shQ[tid] += shQ[tid + off]; }
        __syncthreads();
    }
    if (tid == 0) {
        double S = shS[0], Q = shQ[0];
        const double n = (s == 0) ? (double)BB * 1536.0 : (double)BB * 1024.0;
        double mu  = S / n;
        double var = (Q - S * S / n) / (n - 1.0);
        if (var < 0.0) var = 0.0;
        double sd = sqrt(var);
        if (sd < 1e-4) sd = 1e-4;
        float g  = gamma[s * HH + h];
        float be = beta[s * HH + h];
        float a  = (float)((double)g / sd);
        g_cA[s][h] = a;
        g_cB[s][h] = be - (float)mu * a;
    }
}

extern "C" void kernel_launch(void* const* d_in, const int* in_sizes, int n_in,
                              void* d_out, int out_size) {
    (void)in_sizes; (void)n_in; (void)out_size;
    const float* x     = (const float*)d_in[0];
    const float* alpha = (const float*)d_in[1];
    const float* gamma = (const float*)d_in[2];
    const float* beta  = (const float*)d_in[3];
    float* out = (float*)d_out;

    fan_kernel<false><<<NBLK, HH>>>(x, alpha, nullptr);
    stats_kernel<<<2 * HH, 256>>>(gamma, beta);
    fan_kernel<true><<<NBLK, HH>>>(x, alpha, out);
}